// round 3
// baseline (speedup 1.0000x reference)
#include <cuda_runtime.h>
#include <cuda_bf16.h>
#include <cstdint>
#include <cstddef>
#include <math.h>

// ---------------- problem constants ----------------
#define BTOK  16384
#define IND   512
#define HIDD  2048
#define NEXP  8
#define NTOP  4

// ---------------- tiling ----------------
#define TM      256               // tokens per block
#define TN      128               // hidden cols per block
#define KCH     32                // K per pipeline stage
#define NST     3
#define NKCH    (IND / KCH)       // 16
#define HTILES  (HIDD / TN)       // 16
#define MTILES  (BTOK / TM)       // 64 (worst case)
#define NTHR    512

// smem: padded row stride 36 floats (144B: 16B-aligned rows, conflict-free frags)
#define SROW    36
#define A_BYTES (TM * SROW * 4)               // 36864
#define B_BYTES (TN * SROW * 4)               // 18432
#define STAGE_BYTES (A_BYTES + B_BYTES)       // 55296
#define SMEM_TOTAL  (NST * STAGE_BYTES)       // 165888

// ---------------- device scratch ----------------
__device__ __align__(1024) float g_xc[(size_t)NEXP * BTOK * IND];    // compacted x rows (tf32)
__device__ __align__(1024) float g_w1t[(size_t)NEXP * HIDD * IND];   // W1^T (tf32)
__device__ int   g_cnt[NEXP];
__device__ int   g_sel[BTOK * NTOP];
__device__ int   g_slot[BTOK * NTOP];
__device__ float g_g4[BTOK * NTOP];
__device__ float g_part[(size_t)NEXP * BTOK * HTILES];

// ---------------- helpers ----------------
__device__ __forceinline__ float tf32_rne(float v) {
    uint32_t u;
    asm("cvt.rna.tf32.f32 %0, %1;" : "=r"(u) : "f"(v));
    return __uint_as_float(u);
}

__device__ __forceinline__ uint32_t smem_u32(const void* p) {
    uint32_t a;
    asm("{ .reg .u64 t; cvta.to.shared.u64 t, %1; cvt.u32.u64 %0, t; }" : "=r"(a) : "l"(p));
    return a;
}

__device__ __forceinline__ void cp_async16(uint32_t saddr, const void* gaddr) {
    asm volatile("cp.async.cg.shared.global [%0], [%1], 16;" :: "r"(saddr), "l"(gaddr) : "memory");
}

__device__ __forceinline__ void mma_tf32(float* c, const uint32_t* a, const uint32_t* b) {
    asm volatile(
        "mma.sync.aligned.m16n8k8.row.col.f32.tf32.tf32.f32 "
        "{%0,%1,%2,%3}, {%4,%5,%6,%7}, {%8,%9}, {%0,%1,%2,%3};"
        : "+f"(c[0]), "+f"(c[1]), "+f"(c[2]), "+f"(c[3])
        : "r"(a[0]), "r"(a[1]), "r"(a[2]), "r"(a[3]), "r"(b[0]), "r"(b[1]));
}

// ============================================================
// kernel 0: zero counters
// ============================================================
__global__ void k_zero() {
    if (threadIdx.x < NEXP) g_cnt[threadIdx.x] = 0;
}

// ============================================================
// kernel 1: transpose W1 -> w1t[e][h][i] (tf32-rounded)
// ============================================================
__global__ void k_transpose(const float* __restrict__ W1) {
    __shared__ float tile[32][33];
    int e  = blockIdx.z;
    int i0 = blockIdx.x * 32;
    int h0 = blockIdx.y * 32;
    int tx = threadIdx.x;      // 0..31
    int ty = threadIdx.y;      // 0..7
    #pragma unroll
    for (int r = ty; r < 32; r += 8)
        tile[r][tx] = W1[((size_t)e * IND + (i0 + r)) * HIDD + h0 + tx];
    __syncthreads();
    #pragma unroll
    for (int r = ty; r < 32; r += 8) {
        float v = tile[tx][r];   // W1[e][i0+tx][h0+r]
        g_w1t[((size_t)e * HIDD + h0 + r) * IND + i0 + tx] = tf32_rne(v);
    }
}

// ============================================================
// kernel 2: gating + top-4 + softmax + compaction scatter
// one warp per token
// ============================================================
__global__ void k_gate(const float* __restrict__ x, const float* __restrict__ wg) {
    int warp = blockIdx.x * (blockDim.x >> 5) + (threadIdx.x >> 5);
    int lane = threadIdx.x & 31;
    if (warp >= BTOK) return;
    const float* xr = x + (size_t)warp * IND;

    float acc[NEXP];
    #pragma unroll
    for (int e = 0; e < NEXP; ++e) acc[e] = 0.f;

    for (int i = lane; i < IND; i += 32) {
        float xv = xr[i];
        #pragma unroll
        for (int e = 0; e < NEXP; ++e) acc[e] = fmaf(xv, wg[i * NEXP + e], acc[e]);
    }
    #pragma unroll
    for (int off = 16; off > 0; off >>= 1) {
        #pragma unroll
        for (int e = 0; e < NEXP; ++e)
            acc[e] += __shfl_xor_sync(0xFFFFFFFFu, acc[e], off);
    }

    // top-4: strict '>' keeps lowest index on ties (matches jax.lax.top_k)
    int   sel[NTOP];
    float val[NTOP];
    bool  used[NEXP];
    #pragma unroll
    for (int e = 0; e < NEXP; ++e) used[e] = false;
    #pragma unroll
    for (int k = 0; k < NTOP; ++k) {
        float best = -1e30f; int be = 0;
        #pragma unroll
        for (int e = 0; e < NEXP; ++e)
            if (!used[e] && acc[e] > best) { best = acc[e]; be = e; }
        used[be] = true; sel[k] = be; val[k] = best;
    }
    float s = 0.f, gt[NTOP];
    #pragma unroll
    for (int k = 0; k < NTOP; ++k) { gt[k] = expf(val[k] - val[0]); s += gt[k]; }
    float inv = 1.f / s;
    #pragma unroll
    for (int k = 0; k < NTOP; ++k) gt[k] *= inv;

    int slot[NTOP];
    if (lane == 0) {
        #pragma unroll
        for (int k = 0; k < NTOP; ++k) slot[k] = atomicAdd(&g_cnt[sel[k]], 1);
    }
    #pragma unroll
    for (int k = 0; k < NTOP; ++k) slot[k] = __shfl_sync(0xFFFFFFFFu, slot[k], 0);

    if (lane < NTOP) {
        g_sel[warp * NTOP + lane]  = sel[lane];
        g_slot[warp * NTOP + lane] = slot[lane];
        g_g4[warp * NTOP + lane]   = gt[lane];
    }

    #pragma unroll
    for (int k = 0; k < NTOP; ++k) {
        float* dst = g_xc + ((size_t)sel[k] * BTOK + slot[k]) * IND;
        for (int i = lane; i < IND; i += 32) dst[i] = tf32_rne(xr[i]);
    }
}

// ============================================================
// kernel 3: expert GEMM via mma.sync tf32 (fc1 + relu + fc2-partial)
// grid (HTILES, MTILES, NEXP) -> htiles adjacent share the A tile in L2
// ============================================================
__device__ __forceinline__ void load_stage(uint32_t sb, int s, int k0, int tid,
                                           const float* Ag, const float* Bg) {
    uint32_t abase = sb + (uint32_t)s * STAGE_BYTES;
    uint32_t bbase = abase + A_BYTES;
    // A: TM x KCH floats = 2048 x 16B chunks
    #pragma unroll
    for (int it = 0; it < 4; ++it) {
        int idx = tid + it * NTHR;
        int row = idx >> 3, ch = idx & 7;
        cp_async16(abase + (uint32_t)row * (SROW * 4) + (uint32_t)ch * 16,
                   Ag + (size_t)row * IND + k0 + ch * 4);
    }
    // B: TN x KCH floats = 1024 x 16B chunks
    #pragma unroll
    for (int it = 0; it < 2; ++it) {
        int idx = tid + it * NTHR;
        int row = idx >> 3, ch = idx & 7;
        cp_async16(bbase + (uint32_t)row * (SROW * 4) + (uint32_t)ch * 16,
                   Bg + (size_t)row * IND + k0 + ch * 4);
    }
    asm volatile("cp.async.commit_group;" ::: "memory");
}

__global__ void __launch_bounds__(NTHR, 1)
k_expert(const float* __restrict__ W2, const float* __restrict__ b1) {
    extern __shared__ char smem[];
    const int e     = blockIdx.z;
    const int mtile = blockIdx.y;
    const int ht    = blockIdx.x;
    const int cnt   = g_cnt[e];
    const int m0    = mtile * TM;
    if (m0 >= cnt) return;

    const int tid  = threadIdx.x;
    const int wid  = tid >> 5;
    const int lane = tid & 31;
    const int wm   = wid >> 2;       // 0..3 : rows wm*64
    const int wn   = wid & 3;        // 0..3 : cols wn*32
    const int grp  = lane >> 2;      // 0..7
    const int qid  = lane & 3;       // 0..3

    uint32_t sb = smem_u32(smem);
    const float* Ag = g_xc  + ((size_t)e * BTOK + m0) * IND;
    const float* Bg = g_w1t + ((size_t)e * HIDD + ht * TN) * IND;

    float acc[4][4][4];
    #pragma unroll
    for (int mt = 0; mt < 4; ++mt)
        #pragma unroll
        for (int nt = 0; nt < 4; ++nt)
            #pragma unroll
            for (int r = 0; r < 4; ++r) acc[mt][nt][r] = 0.f;

    // prologue: stages 0,1
    load_stage(sb, 0, 0, tid, Ag, Bg);
    load_stage(sb, 1, KCH, tid, Ag, Bg);

    for (int kt = 0; kt < NKCH; ++kt) {
        asm volatile("cp.async.wait_group 1;" ::: "memory");
        __syncthreads();
        int kn = kt + 2;
        if (kn < NKCH) load_stage(sb, kn % NST, kn * KCH, tid, Ag, Bg);
        else asm volatile("cp.async.commit_group;" ::: "memory");

        const float* sA = (const float*)(smem + (size_t)(kt % NST) * STAGE_BYTES);
        const float* sB = (const float*)(smem + (size_t)(kt % NST) * STAGE_BYTES + A_BYTES);

        #pragma unroll
        for (int ks = 0; ks < 4; ++ks) {            // 4 K=8 steps
            int kc = ks * 8 + qid;
            uint32_t af[4][4];
            #pragma unroll
            for (int mt = 0; mt < 4; ++mt) {
                int r0 = wm * 64 + mt * 16 + grp;
                af[mt][0] = __float_as_uint(sA[r0 * SROW + kc]);
                af[mt][1] = __float_as_uint(sA[(r0 + 8) * SROW + kc]);
                af[mt][2] = __float_as_uint(sA[r0 * SROW + kc + 4]);
                af[mt][3] = __float_as_uint(sA[(r0 + 8) * SROW + kc + 4]);
            }
            uint32_t bf[4][2];
            #pragma unroll
            for (int nt = 0; nt < 4; ++nt) {
                int n = wn * 32 + nt * 8 + grp;
                bf[nt][0] = __float_as_uint(sB[n * SROW + kc]);
                bf[nt][1] = __float_as_uint(sB[n * SROW + kc + 4]);
            }
            #pragma unroll
            for (int mt = 0; mt < 4; ++mt)
                #pragma unroll
                for (int nt = 0; nt < 4; ++nt)
                    mma_tf32(acc[mt][nt], af[mt], bf[nt]);
        }
        __syncthreads();
    }

    // ---- fused epilogue: relu(h + b1) . W2 over this 128-col tile ----
    float* red = (float*)smem;                 // [TM][4]  (row, wn)
    float* w2s = (float*)(smem + TM * 4 * 4);  // [TN]
    float* b1s = w2s + TN;                     // [TN]
    if (tid < TN) {
        w2s[tid] = W2[(size_t)e * HIDD + ht * TN + tid];
        b1s[tid] = b1[(size_t)e * HIDD + ht * TN + tid];
    }
    __syncthreads();

    #pragma unroll
    for (int mt = 0; mt < 4; ++mt) {
        #pragma unroll
        for (int rr = 0; rr < 2; ++rr) {
            int row = wm * 64 + mt * 16 + grp + rr * 8;
            float v = 0.f;
            #pragma unroll
            for (int nt = 0; nt < 4; ++nt) {
                int col = wn * 32 + nt * 8 + qid * 2;
                float h0 = fmaxf(acc[mt][nt][rr * 2 + 0] + b1s[col], 0.f);
                float h1 = fmaxf(acc[mt][nt][rr * 2 + 1] + b1s[col + 1], 0.f);
                v = fmaf(h0, w2s[col], v);
                v = fmaf(h1, w2s[col + 1], v);
            }
            // reduce over qid (4 lanes, consecutive)
            v += __shfl_down_sync(0xFFFFFFFFu, v, 2);
            v += __shfl_down_sync(0xFFFFFFFFu, v, 1);
            if (qid == 0) red[row * 4 + wn] = v;
        }
    }
    __syncthreads();

    if (tid < TM) {
        float p = red[tid * 4 + 0] + red[tid * 4 + 1] + red[tid * 4 + 2] + red[tid * 4 + 3];
        g_part[((size_t)e * BTOK + m0 + tid) * HTILES + ht] = p;
    }
}

// ============================================================
// kernel 4: weighted combine
// ============================================================
__global__ void k_combine(float* __restrict__ out, const float* __restrict__ b2) {
    int t = blockIdx.x * blockDim.x + threadIdx.x;
    if (t >= BTOK) return;
    float y = 0.f;
    #pragma unroll
    for (int k = 0; k < NTOP; ++k) {
        int   e = g_sel[t * NTOP + k];
        int   s = g_slot[t * NTOP + k];
        float g = g_g4[t * NTOP + k];
        float p = b2[e];
        const float* pp = &g_part[((size_t)e * BTOK + s) * HTILES];
        #pragma unroll
        for (int h = 0; h < HTILES; ++h) p += pp[h];
        y = fmaf(g, p, y);
    }
    out[t] = y;
}

// ============================================================
// launch
// ============================================================
extern "C" void kernel_launch(void* const* d_in, const int* in_sizes, int n_in,
                              void* d_out, int out_size) {
    const float* x  = (const float*)d_in[0];   // [16384, 512]
    const float* wg = (const float*)d_in[1];   // [512, 8]
    const float* W1 = (const float*)d_in[2];   // [8, 512, 2048]
    const float* b1 = (const float*)d_in[3];   // [8, 2048]
    const float* W2 = (const float*)d_in[4];   // [8, 2048, 1]
    const float* b2 = (const float*)d_in[5];   // [8, 1]
    float* out = (float*)d_out;                // [16384, 1]

    cudaFuncSetAttribute(k_expert, cudaFuncAttributeMaxDynamicSharedMemorySize, SMEM_TOTAL);

    k_zero<<<1, 32>>>();
    k_transpose<<<dim3(IND / 32, HIDD / 32, NEXP), dim3(32, 8)>>>(W1);
    k_gate<<<BTOK / 8, 256>>>(x, wg);
    k_expert<<<dim3(HTILES, MTILES, NEXP), NTHR, SMEM_TOTAL>>>(W2, b1);
    k_combine<<<(BTOK + 255) / 256, 256>>>(out, b2);
}

// round 4
// speedup vs baseline: 1.1694x; 1.1694x over previous
#include <cuda_runtime.h>
#include <cuda_bf16.h>
#include <cstdint>
#include <cstddef>
#include <math.h>

// ---------------- problem constants ----------------
#define BTOK  16384
#define IND   512
#define HIDD  2048
#define NEXP  8
#define NTOP  4

// ---------------- tiling ----------------
#define TM      256               // tokens per block
#define TN      128               // hidden cols per block
#define KCH     32                // K per pipeline stage (4 k-blocks of 8)
#define NST     3
#define NKCH    (IND / KCH)       // 16
#define NKB     (IND / 8)         // 64 k-blocks total
#define HTILES  (HIDD / TN)       // 16
#define MTILES  (BTOK / TM)       // 64 (worst case)
#define NTHR    512

// packed-fragment stage sizes
// A stage: 16 m-tiles x 4 kb x 32 lanes x float4 = 32768 B
// B stage: 16 h8-tiles x 4 kb x 32 lanes x float2 = 16384 B
#define A_BYTES 32768
#define B_BYTES 16384
#define STAGE_BYTES (A_BYTES + B_BYTES)       // 49152
#define SMEM_TOTAL  (NST * STAGE_BYTES)       // 147456

// ---------------- device scratch ----------------
// A packed: [e][slot/16][kb][lane][4]  (elem: 0=(g,q) 1=(g+8,q) 2=(g,q+4) 3=(g+8,q+4))
__device__ __align__(1024) float g_xc[(size_t)NEXP * BTOK * IND];
// B packed: [e][h/8][kb][lane][2]      (elem: 0=(rh,q) 1=(rh,q+4))
__device__ __align__(1024) float g_w1t[(size_t)NEXP * HIDD * IND];
__device__ int   g_cnt[NEXP];
__device__ int   g_sel[BTOK * NTOP];
__device__ int   g_slot[BTOK * NTOP];
__device__ float g_g4[BTOK * NTOP];
__device__ float g_part[(size_t)NEXP * BTOK * HTILES];

// ---------------- helpers ----------------
__device__ __forceinline__ float tf32_rne(float v) {
    uint32_t u;
    asm("cvt.rna.tf32.f32 %0, %1;" : "=r"(u) : "f"(v));
    return __uint_as_float(u);
}

__device__ __forceinline__ void cp_async16(uint32_t saddr, const void* gaddr) {
    asm volatile("cp.async.cg.shared.global [%0], [%1], 16;" :: "r"(saddr), "l"(gaddr) : "memory");
}

__device__ __forceinline__ uint32_t smem_u32(const void* p) {
    uint32_t a;
    asm("{ .reg .u64 t; cvta.to.shared.u64 t, %1; cvt.u32.u64 %0, t; }" : "=r"(a) : "l"(p));
    return a;
}

__device__ __forceinline__ void mma_tf32(float* c, const uint32_t* a, const uint32_t* b) {
    asm volatile(
        "mma.sync.aligned.m16n8k8.row.col.f32.tf32.tf32.f32 "
        "{%0,%1,%2,%3}, {%4,%5,%6,%7}, {%8,%9}, {%0,%1,%2,%3};"
        : "+f"(c[0]), "+f"(c[1]), "+f"(c[2]), "+f"(c[3])
        : "r"(a[0]), "r"(a[1]), "r"(a[2]), "r"(a[3]), "r"(b[0]), "r"(b[1]));
}

// ============================================================
// kernel 0: zero counters
// ============================================================
__global__ void k_zero() {
    if (threadIdx.x < NEXP) g_cnt[threadIdx.x] = 0;
}

// ============================================================
// kernel 1: W1 -> packed-fragment B layout (tf32-rounded)
// grid (8 hchunks, 64 kb, 8 e), 256 thr, 8 outputs each
// ============================================================
__global__ void k_transpose(const float* __restrict__ W1) {
    int hc = blockIdx.x;           // 256-h chunk
    int kb = blockIdx.y;
    int e  = blockIdx.z;
    int h0   = hc * 256;
    int ht80 = hc * 32;
    size_t wbase = (size_t)e * HIDD * IND;
    #pragma unroll
    for (int i = 0; i < 8; ++i) {
        int j    = threadIdx.x + i * 256;     // 0..2047
        int ht8l = j >> 6;
        int rem  = j & 63;
        int lane = rem >> 1, el = rem & 1;
        int rh   = lane >> 2, qid = lane & 3;
        int kc   = el * 4 + qid;
        int h    = h0 + ht8l * 8 + rh;
        int k    = kb * 8 + kc;
        float v  = W1[((size_t)e * IND + k) * HIDD + h];
        g_w1t[wbase + ((size_t)(ht80 + ht8l) * NKB + kb) * 64 + rem] = tf32_rne(v);
    }
}

// ============================================================
// kernel 2: gating + top-4 + softmax + packed-fragment scatter
// one warp per token
// ============================================================
__global__ void k_gate(const float* __restrict__ x, const float* __restrict__ wg) {
    int warp = blockIdx.x * (blockDim.x >> 5) + (threadIdx.x >> 5);
    int lane = threadIdx.x & 31;
    if (warp >= BTOK) return;
    const float* xr = x + (size_t)warp * IND;

    float acc[NEXP];
    #pragma unroll
    for (int e = 0; e < NEXP; ++e) acc[e] = 0.f;
    for (int i = lane; i < IND; i += 32) {
        float xv = xr[i];
        #pragma unroll
        for (int e = 0; e < NEXP; ++e) acc[e] = fmaf(xv, wg[i * NEXP + e], acc[e]);
    }
    #pragma unroll
    for (int off = 16; off > 0; off >>= 1) {
        #pragma unroll
        for (int e = 0; e < NEXP; ++e)
            acc[e] += __shfl_xor_sync(0xFFFFFFFFu, acc[e], off);
    }

    // top-4: strict '>' keeps lowest index on ties (matches jax.lax.top_k)
    int   sel[NTOP];
    float val[NTOP];
    bool  used[NEXP];
    #pragma unroll
    for (int e = 0; e < NEXP; ++e) used[e] = false;
    #pragma unroll
    for (int k = 0; k < NTOP; ++k) {
        float best = -1e30f; int be = 0;
        #pragma unroll
        for (int e = 0; e < NEXP; ++e)
            if (!used[e] && acc[e] > best) { best = acc[e]; be = e; }
        used[be] = true; sel[k] = be; val[k] = best;
    }
    float s = 0.f, gt[NTOP];
    #pragma unroll
    for (int k = 0; k < NTOP; ++k) { gt[k] = expf(val[k] - val[0]); s += gt[k]; }
    float inv = 1.f / s;
    #pragma unroll
    for (int k = 0; k < NTOP; ++k) gt[k] *= inv;

    int slot[NTOP];
    if (lane == 0) {
        #pragma unroll
        for (int k = 0; k < NTOP; ++k) slot[k] = atomicAdd(&g_cnt[sel[k]], 1);
    }
    #pragma unroll
    for (int k = 0; k < NTOP; ++k) slot[k] = __shfl_sync(0xFFFFFFFFu, slot[k], 0);

    if (lane < NTOP) {
        g_sel[warp * NTOP + lane]  = sel[lane];
        g_slot[warp * NTOP + lane] = slot[lane];
        g_g4[warp * NTOP + lane]   = gt[lane];
    }

    // scatter tf32 x row into each selected expert's packed-fragment buffer
    #pragma unroll
    for (int kk = 0; kk < NTOP; ++kk) {
        int sl = slot[kk];
        float* dst = g_xc + (size_t)sel[kk] * BTOK * IND + (size_t)(sl >> 4) * (NKB * 128);
        int r = sl & 15, grp = r & 7, half = r >> 3;
        #pragma unroll
        for (int it = 0; it < IND / 32; ++it) {
            int i  = lane + it * 32;
            int kb = i >> 3, kc = i & 7;
            dst[(size_t)kb * 128 + (grp * 4 + (kc & 3)) * 4 + (kc >> 2) * 2 + half]
                = tf32_rne(xr[i]);
        }
    }
}

// ============================================================
// kernel 3: expert GEMM (fc1 + relu + fc2-partial), packed frags
// grid (HTILES, MTILES, NEXP)
// ============================================================
__device__ __forceinline__ void load_stage(uint32_t sb, int s, int kt, int tid,
                                           const float* Ag, const float* Bg) {
    uint32_t abase = sb + (uint32_t)s * STAGE_BYTES;
    uint32_t bbase = abase + A_BYTES;
    // A: 2048 chunks of 16B; gmem per tile stride = NKB*128 floats
    #pragma unroll
    for (int it = 0; it < 4; ++it) {
        int c    = tid + it * NTHR;
        int tile = c >> 7, rem = c & 127;
        cp_async16(abase + (uint32_t)c * 16,
                   Ag + (size_t)tile * (NKB * 128) + kt * 512 + rem * 4);
    }
    // B: 1024 chunks of 16B; gmem per h8-tile stride = NKB*64 floats
    #pragma unroll
    for (int it = 0; it < 2; ++it) {
        int c    = tid + it * NTHR;
        int tile = c >> 6, rem = c & 63;
        cp_async16(bbase + (uint32_t)c * 16,
                   Bg + (size_t)tile * (NKB * 64) + kt * 256 + rem * 4);
    }
    asm volatile("cp.async.commit_group;" ::: "memory");
}

__global__ void __launch_bounds__(NTHR, 1)
k_expert(const float* __restrict__ W2, const float* __restrict__ b1) {
    extern __shared__ char smem[];
    const int e     = blockIdx.z;
    const int mtile = blockIdx.y;
    const int ht    = blockIdx.x;
    const int cnt   = g_cnt[e];
    const int m0    = mtile * TM;
    if (m0 >= cnt) return;

    const int tid  = threadIdx.x;
    const int wid  = tid >> 5;
    const int lane = tid & 31;
    const int wm   = wid >> 2;       // rows wm*64
    const int wn   = wid & 3;        // cols wn*32
    const int grp  = lane >> 2;
    const int qid  = lane & 3;

    uint32_t sb = smem_u32(smem);
    const float* Ag = g_xc  + (size_t)e * BTOK * IND + (size_t)(m0 >> 4) * (NKB * 128);
    const float* Bg = g_w1t + (size_t)e * HIDD * IND + (size_t)(ht * (TN / 8)) * (NKB * 64);

    float acc[4][4][4];
    #pragma unroll
    for (int mt = 0; mt < 4; ++mt)
        #pragma unroll
        for (int nt = 0; nt < 4; ++nt)
            #pragma unroll
            for (int r = 0; r < 4; ++r) acc[mt][nt][r] = 0.f;

    load_stage(sb, 0, 0, tid, Ag, Bg);
    load_stage(sb, 1, 1, tid, Ag, Bg);

    for (int kt = 0; kt < NKCH; ++kt) {
        asm volatile("cp.async.wait_group 1;" ::: "memory");
        __syncthreads();
        int kn = kt + 2;
        if (kn < NKCH) load_stage(sb, kn % NST, kn, tid, Ag, Bg);
        else asm volatile("cp.async.commit_group;" ::: "memory");

        const float4* sA = (const float4*)(smem + (size_t)(kt % NST) * STAGE_BYTES);
        const float2* sB = (const float2*)(smem + (size_t)(kt % NST) * STAGE_BYTES + A_BYTES);

        #pragma unroll
        for (int ks = 0; ks < 4; ++ks) {                 // 4 K=8 steps
            float4 af[4];
            float2 bf[4];
            #pragma unroll
            for (int mt = 0; mt < 4; ++mt)
                af[mt] = sA[((wm * 4 + mt) * 4 + ks) * 32 + lane];
            #pragma unroll
            for (int nt = 0; nt < 4; ++nt)
                bf[nt] = sB[((wn * 4 + nt) * 4 + ks) * 32 + lane];
            #pragma unroll
            for (int mt = 0; mt < 4; ++mt)
                #pragma unroll
                for (int nt = 0; nt < 4; ++nt)
                    mma_tf32(acc[mt][nt], (const uint32_t*)&af[mt], (const uint32_t*)&bf[nt]);
        }
        __syncthreads();
    }

    // ---- fused epilogue: relu(h + b1) . W2 over this 128-col tile ----
    float* red = (float*)smem;                 // [TM][4]
    float* w2s = (float*)(smem + TM * 4 * 4);  // [TN]
    float* b1s = w2s + TN;                     // [TN]
    if (tid < TN) {
        w2s[tid] = W2[(size_t)e * HIDD + ht * TN + tid];
        b1s[tid] = b1[(size_t)e * HIDD + ht * TN + tid];
    }
    __syncthreads();

    #pragma unroll
    for (int mt = 0; mt < 4; ++mt) {
        #pragma unroll
        for (int rr = 0; rr < 2; ++rr) {
            int row = wm * 64 + mt * 16 + grp + rr * 8;
            float v = 0.f;
            #pragma unroll
            for (int nt = 0; nt < 4; ++nt) {
                int col = wn * 32 + nt * 8 + qid * 2;
                float h0 = fmaxf(acc[mt][nt][rr * 2 + 0] + b1s[col], 0.f);
                float h1 = fmaxf(acc[mt][nt][rr * 2 + 1] + b1s[col + 1], 0.f);
                v = fmaf(h0, w2s[col], v);
                v = fmaf(h1, w2s[col + 1], v);
            }
            v += __shfl_down_sync(0xFFFFFFFFu, v, 2);
            v += __shfl_down_sync(0xFFFFFFFFu, v, 1);
            if (qid == 0) red[row * 4 + wn] = v;
        }
    }
    __syncthreads();

    if (tid < TM) {
        float p = red[tid * 4 + 0] + red[tid * 4 + 1] + red[tid * 4 + 2] + red[tid * 4 + 3];
        g_part[((size_t)e * BTOK + m0 + tid) * HTILES + ht] = p;
    }
}

// ============================================================
// kernel 4: weighted combine
// ============================================================
__global__ void k_combine(float* __restrict__ out, const float* __restrict__ b2) {
    int t = blockIdx.x * blockDim.x + threadIdx.x;
    if (t >= BTOK) return;
    float y = 0.f;
    #pragma unroll
    for (int k = 0; k < NTOP; ++k) {
        int   e = g_sel[t * NTOP + k];
        int   s = g_slot[t * NTOP + k];
        float g = g_g4[t * NTOP + k];
        float p = b2[e];
        const float* pp = &g_part[((size_t)e * BTOK + s) * HTILES];
        #pragma unroll
        for (int h = 0; h < HTILES; ++h) p += pp[h];
        y = fmaf(g, p, y);
    }
    out[t] = y;
}

// ============================================================
// launch
// ============================================================
extern "C" void kernel_launch(void* const* d_in, const int* in_sizes, int n_in,
                              void* d_out, int out_size) {
    const float* x  = (const float*)d_in[0];   // [16384, 512]
    const float* wg = (const float*)d_in[1];   // [512, 8]
    const float* W1 = (const float*)d_in[2];   // [8, 512, 2048]
    const float* b1 = (const float*)d_in[3];   // [8, 2048]
    const float* W2 = (const float*)d_in[4];   // [8, 2048, 1]
    const float* b2 = (const float*)d_in[5];   // [8, 1]
    float* out = (float*)d_out;                // [16384, 1]

    cudaFuncSetAttribute(k_expert, cudaFuncAttributeMaxDynamicSharedMemorySize, SMEM_TOTAL);

    k_zero<<<1, 32>>>();
    k_transpose<<<dim3(HIDD / 256, NKB, NEXP), 256>>>(W1);
    k_gate<<<BTOK / 8, 256>>>(x, wg);
    k_expert<<<dim3(HTILES, MTILES, NEXP), NTHR, SMEM_TOTAL>>>(W2, b1);
    k_combine<<<(BTOK + 255) / 256, 256>>>(out, b2);
}

// round 5
// speedup vs baseline: 1.9678x; 1.6827x over previous
#include <cuda_runtime.h>
#include <cuda_fp16.h>
#include <cstdint>
#include <cstddef>
#include <math.h>

// ---------------- problem constants ----------------
#define BTOK  16384
#define IND   512
#define HIDD  2048
#define NEXP  8
#define NTOP  4

// ---------------- tiling ----------------
#define TM      256               // tokens per block
#define TN      128               // hidden cols per block
#define NKB     (IND / 16)        // 32 k-blocks of K=16
#define KBPST   4                 // k-blocks per stage (K=64)
#define NST     3
#define NKCH    (NKB / KBPST)     // 8 mainloop iterations
#define HTILES  (HIDD / TN)       // 16
#define MTILES  (BTOK / TM)       // 64 (worst case)
#define NTHR    512

// packed-fragment stage sizes (fp16)
// A stage: 16 m-tiles x 4 kb x 32 lanes x 16B (4 half2-regs) = 32768 B
// B stage: 16 h8-tiles x 4 kb x 32 lanes x 8B (2 half2-regs) = 16384 B
#define A_BYTES 32768
#define B_BYTES 16384
#define STAGE_BYTES (A_BYTES + B_BYTES)       // 49152
#define SMEM_TOTAL  (NST * STAGE_BYTES)       // 147456

#define A_TILE_BYTES  16384    // one 16-row m-tile: 32 kb x 32 lanes x 16B
#define B_TILE_BYTES  8192     // one 8-col h-tile: 32 kb x 32 lanes x 8B

// ---------------- device scratch ----------------
// A packed (half2 as uint): [e][slot/16][kb][lane][4]
//   reg j: row = grp + 8*(j&1); k = kb*16 + 8*(j>>1) + 2*qid + {0,1}
__device__ __align__(1024) uint32_t g_xcu[(size_t)NEXP * BTOK * IND / 2];
// B packed (half2 as uint): [e][h/8][kb][lane][2]
//   reg j: col = grp; k = kb*16 + 8*j + 2*qid + {0,1}
__device__ __align__(1024) uint32_t g_w1u[(size_t)NEXP * HIDD * IND / 2];
__device__ int   g_cnt[NEXP];
__device__ int   g_sel[BTOK * NTOP];
__device__ int   g_slot[BTOK * NTOP];
__device__ float g_g4[BTOK * NTOP];
__device__ float g_part[(size_t)NEXP * BTOK * HTILES];

// ---------------- helpers ----------------
__device__ __forceinline__ void cp_async16(uint32_t saddr, const void* gaddr) {
    asm volatile("cp.async.cg.shared.global [%0], [%1], 16;" :: "r"(saddr), "l"(gaddr) : "memory");
}

__device__ __forceinline__ uint32_t smem_u32(const void* p) {
    uint32_t a;
    asm("{ .reg .u64 t; cvta.to.shared.u64 t, %1; cvt.u32.u64 %0, t; }" : "=r"(a) : "l"(p));
    return a;
}

__device__ __forceinline__ void mma_f16(float* c, const uint32_t* a, const uint32_t* b) {
    asm volatile(
        "mma.sync.aligned.m16n8k16.row.col.f32.f16.f16.f32 "
        "{%0,%1,%2,%3}, {%4,%5,%6,%7}, {%8,%9}, {%0,%1,%2,%3};"
        : "+f"(c[0]), "+f"(c[1]), "+f"(c[2]), "+f"(c[3])
        : "r"(a[0]), "r"(a[1]), "r"(a[2]), "r"(a[3]), "r"(b[0]), "r"(b[1]));
}

// ============================================================
// kernel 0: zero counters
// ============================================================
__global__ void k_zero() {
    if (threadIdx.x < NEXP) g_cnt[threadIdx.x] = 0;
}

// ============================================================
// kernel 1: W1 -> packed fp16 B-fragment layout
// grid (16 h-chunks of 128, 32 kb, 8 e), 256 thr
// ============================================================
__global__ void k_transpose(const float* __restrict__ W1) {
    __shared__ float tile[16][129];
    int hc = blockIdx.x;      // 128-h chunk
    int kb = blockIdx.y;
    int e  = blockIdx.z;
    int tid = threadIdx.x;

    // coalesced load: 16 k-rows x 128 h
    #pragma unroll
    for (int it = 0; it < 8; ++it) {
        int idx = tid + it * 256;
        int kr = idx >> 7, hf = idx & 127;
        tile[kr][hf] = W1[((size_t)e * IND + kb * 16 + kr) * HIDD + hc * 128 + hf];
    }
    __syncthreads();

    // packed store: 1024 half2
    size_t base2 = (size_t)e * (HIDD * IND / 2);
    #pragma unroll
    for (int it = 0; it < 4; ++it) {
        int w    = tid + it * 256;
        int h8l  = w >> 6;
        int rem  = w & 63;
        int lane = rem >> 1, rj = rem & 1;
        int grp  = lane >> 2, qid = lane & 3;
        int hl   = h8l * 8 + grp;
        int k0   = rj * 8 + qid * 2;
        __half2 v = __floats2half2_rn(tile[k0][hl], tile[k0 + 1][hl]);
        g_w1u[base2 + (size_t)(hc * 16 + h8l) * 2048 + (kb * 32 + lane) * 2 + rj]
            = *(uint32_t*)&v;
    }
}

// ============================================================
// kernel 2: gating + top-4 + softmax + packed fp16 scatter
// one warp per token
// ============================================================
__global__ void k_gate(const float* __restrict__ x, const float* __restrict__ wg) {
    int warp = blockIdx.x * (blockDim.x >> 5) + (threadIdx.x >> 5);
    int lane = threadIdx.x & 31;
    if (warp >= BTOK) return;
    const float* xr = x + (size_t)warp * IND;

    float acc[NEXP];
    #pragma unroll
    for (int e = 0; e < NEXP; ++e) acc[e] = 0.f;
    for (int i = lane; i < IND; i += 32) {
        float xv = xr[i];
        #pragma unroll
        for (int e = 0; e < NEXP; ++e) acc[e] = fmaf(xv, wg[i * NEXP + e], acc[e]);
    }
    #pragma unroll
    for (int off = 16; off > 0; off >>= 1) {
        #pragma unroll
        for (int e = 0; e < NEXP; ++e)
            acc[e] += __shfl_xor_sync(0xFFFFFFFFu, acc[e], off);
    }

    // top-4: strict '>' keeps lowest index on ties (matches jax.lax.top_k)
    int   sel[NTOP];
    float val[NTOP];
    bool  used[NEXP];
    #pragma unroll
    for (int e = 0; e < NEXP; ++e) used[e] = false;
    #pragma unroll
    for (int k = 0; k < NTOP; ++k) {
        float best = -1e30f; int be = 0;
        #pragma unroll
        for (int e = 0; e < NEXP; ++e)
            if (!used[e] && acc[e] > best) { best = acc[e]; be = e; }
        used[be] = true; sel[k] = be; val[k] = best;
    }
    float s = 0.f, gt[NTOP];
    #pragma unroll
    for (int k = 0; k < NTOP; ++k) { gt[k] = expf(val[k] - val[0]); s += gt[k]; }
    float inv = 1.f / s;
    #pragma unroll
    for (int k = 0; k < NTOP; ++k) gt[k] *= inv;

    int slot[NTOP];
    if (lane == 0) {
        #pragma unroll
        for (int k = 0; k < NTOP; ++k) slot[k] = atomicAdd(&g_cnt[sel[k]], 1);
    }
    #pragma unroll
    for (int k = 0; k < NTOP; ++k) slot[k] = __shfl_sync(0xFFFFFFFFu, slot[k], 0);

    if (lane < NTOP) {
        g_sel[warp * NTOP + lane]  = sel[lane];
        g_slot[warp * NTOP + lane] = slot[lane];
        g_g4[warp * NTOP + lane]   = gt[lane];
    }

    // pre-round row to half2 pairs (shared across the 4 experts)
    uint32_t hv[8];
    #pragma unroll
    for (int it = 0; it < 8; ++it) {
        int p = lane + it * 32;         // half2 index 0..255
        __half2 v = __floats2half2_rn(xr[2 * p], xr[2 * p + 1]);
        hv[it] = *(uint32_t*)&v;
    }

    #pragma unroll
    for (int kk = 0; kk < NTOP; ++kk) {
        int sl = slot[kk];
        size_t base2 = (size_t)sel[kk] * (BTOK * IND / 2) + (size_t)(sl >> 4) * 4096;
        int r = sl & 15, grp = r & 7, rowhalf = r >> 3;
        #pragma unroll
        for (int it = 0; it < 8; ++it) {
            int p     = lane + it * 32;
            int kb    = p >> 3;
            int khalf = (p & 7) >> 2;
            int qid   = p & 3;
            g_xcu[base2 + (size_t)(kb * 32 + grp * 4 + qid) * 4 + rowhalf + 2 * khalf]
                = hv[it];
        }
    }
}

// ============================================================
// kernel 3: expert GEMM fp16 m16n8k16 (fc1 + relu + fc2-partial)
// grid (HTILES, MTILES, NEXP)
// ============================================================
__device__ __forceinline__ void load_stage(uint32_t sb, int s, int kt, int tid,
                                           const char* Ag, const char* Bg) {
    uint32_t abase = sb + (uint32_t)s * STAGE_BYTES;
    uint32_t bbase = abase + A_BYTES;
    // A: 2048 chunks of 16B
    #pragma unroll
    for (int it = 0; it < 4; ++it) {
        int c    = tid + it * NTHR;
        int tile = c >> 7, rem = c & 127;
        cp_async16(abase + (uint32_t)c * 16,
                   Ag + (size_t)tile * A_TILE_BYTES + kt * 2048 + rem * 16);
    }
    // B: 1024 chunks of 16B
    #pragma unroll
    for (int it = 0; it < 2; ++it) {
        int c    = tid + it * NTHR;
        int tile = c >> 6, rem = c & 63;
        cp_async16(bbase + (uint32_t)c * 16,
                   Bg + (size_t)tile * B_TILE_BYTES + kt * 1024 + rem * 16);
    }
    asm volatile("cp.async.commit_group;" ::: "memory");
}

__global__ void __launch_bounds__(NTHR, 1)
k_expert(const float* __restrict__ W2, const float* __restrict__ b1) {
    extern __shared__ char smem[];
    const int e     = blockIdx.z;
    const int mtile = blockIdx.y;
    const int ht    = blockIdx.x;
    const int cnt   = g_cnt[e];
    const int m0    = mtile * TM;
    if (m0 >= cnt) return;

    const int tid  = threadIdx.x;
    const int wid  = tid >> 5;
    const int lane = tid & 31;
    const int wm   = wid >> 2;       // rows wm*64
    const int wn   = wid & 3;        // cols wn*32
    const int grp  = lane >> 2;
    const int qid  = lane & 3;

    uint32_t sb = smem_u32(smem);
    const char* Ag = (const char*)g_xcu + (size_t)e * (BTOK * IND * 2)
                   + (size_t)(m0 >> 4) * A_TILE_BYTES;
    const char* Bg = (const char*)g_w1u + (size_t)e * (HIDD * IND * 2)
                   + (size_t)(ht * (TN / 8)) * B_TILE_BYTES;

    float acc[4][4][4];
    #pragma unroll
    for (int mt = 0; mt < 4; ++mt)
        #pragma unroll
        for (int nt = 0; nt < 4; ++nt)
            #pragma unroll
            for (int r = 0; r < 4; ++r) acc[mt][nt][r] = 0.f;

    load_stage(sb, 0, 0, tid, Ag, Bg);
    load_stage(sb, 1, 1, tid, Ag, Bg);

    for (int kt = 0; kt < NKCH; ++kt) {
        asm volatile("cp.async.wait_group 1;" ::: "memory");
        __syncthreads();
        int kn = kt + 2;
        if (kn < NKCH) load_stage(sb, kn % NST, kn, tid, Ag, Bg);
        else asm volatile("cp.async.commit_group;" ::: "memory");

        const uint4* sA = (const uint4*)(smem + (size_t)(kt % NST) * STAGE_BYTES);
        const uint2* sB = (const uint2*)(smem + (size_t)(kt % NST) * STAGE_BYTES + A_BYTES);

        #pragma unroll
        for (int ks = 0; ks < KBPST; ++ks) {             // 4 K=16 steps
            uint4 af[4];
            uint2 bf[4];
            #pragma unroll
            for (int mt = 0; mt < 4; ++mt)
                af[mt] = sA[((wm * 4 + mt) * 4 + ks) * 32 + lane];
            #pragma unroll
            for (int nt = 0; nt < 4; ++nt)
                bf[nt] = sB[((wn * 4 + nt) * 4 + ks) * 32 + lane];
            #pragma unroll
            for (int mt = 0; mt < 4; ++mt)
                #pragma unroll
                for (int nt = 0; nt < 4; ++nt)
                    mma_f16(acc[mt][nt], (const uint32_t*)&af[mt], (const uint32_t*)&bf[nt]);
        }
        // no trailing barrier needed: next iteration's top barrier precedes the
        // overwrite of slot (kt+2)%3, whose previous contents (stage kt-1) were
        // consumed before that barrier.
    }
    __syncthreads();

    // ---- fused epilogue: relu(h + b1) . W2 over this 128-col tile ----
    float* red = (float*)smem;                 // [TM][4]
    float* w2s = (float*)(smem + TM * 4 * 4);  // [TN]
    float* b1s = w2s + TN;                     // [TN]
    if (tid < TN) {
        w2s[tid] = W2[(size_t)e * HIDD + ht * TN + tid];
        b1s[tid] = b1[(size_t)e * HIDD + ht * TN + tid];
    }
    __syncthreads();

    #pragma unroll
    for (int mt = 0; mt < 4; ++mt) {
        #pragma unroll
        for (int rr = 0; rr < 2; ++rr) {
            int row = wm * 64 + mt * 16 + grp + rr * 8;
            float v = 0.f;
            #pragma unroll
            for (int nt = 0; nt < 4; ++nt) {
                int col = wn * 32 + nt * 8 + qid * 2;
                float h0 = fmaxf(acc[mt][nt][rr * 2 + 0] + b1s[col], 0.f);
                float h1 = fmaxf(acc[mt][nt][rr * 2 + 1] + b1s[col + 1], 0.f);
                v = fmaf(h0, w2s[col], v);
                v = fmaf(h1, w2s[col + 1], v);
            }
            v += __shfl_down_sync(0xFFFFFFFFu, v, 2);
            v += __shfl_down_sync(0xFFFFFFFFu, v, 1);
            if (qid == 0) red[row * 4 + wn] = v;
        }
    }
    __syncthreads();

    if (tid < TM) {
        float p = red[tid * 4 + 0] + red[tid * 4 + 1] + red[tid * 4 + 2] + red[tid * 4 + 3];
        g_part[((size_t)e * BTOK + m0 + tid) * HTILES + ht] = p;
    }
}

// ============================================================
// kernel 4: weighted combine
// ============================================================
__global__ void k_combine(float* __restrict__ out, const float* __restrict__ b2) {
    int t = blockIdx.x * blockDim.x + threadIdx.x;
    if (t >= BTOK) return;
    float y = 0.f;
    #pragma unroll
    for (int k = 0; k < NTOP; ++k) {
        int   e = g_sel[t * NTOP + k];
        int   s = g_slot[t * NTOP + k];
        float g = g_g4[t * NTOP + k];
        float p = b2[e];
        const float* pp = &g_part[((size_t)e * BTOK + s) * HTILES];
        #pragma unroll
        for (int h = 0; h < HTILES; ++h) p += pp[h];
        y = fmaf(g, p, y);
    }
    out[t] = y;
}

// ============================================================
// launch
// ============================================================
extern "C" void kernel_launch(void* const* d_in, const int* in_sizes, int n_in,
                              void* d_out, int out_size) {
    const float* x  = (const float*)d_in[0];   // [16384, 512]
    const float* wg = (const float*)d_in[1];   // [512, 8]
    const float* W1 = (const float*)d_in[2];   // [8, 512, 2048]
    const float* b1 = (const float*)d_in[3];   // [8, 2048]
    const float* W2 = (const float*)d_in[4];   // [8, 2048, 1]
    const float* b2 = (const float*)d_in[5];   // [8, 1]
    float* out = (float*)d_out;                // [16384, 1]

    cudaFuncSetAttribute(k_expert, cudaFuncAttributeMaxDynamicSharedMemorySize, SMEM_TOTAL);

    k_zero<<<1, 32>>>();
    k_transpose<<<dim3(HIDD / 128, NKB, NEXP), 256>>>(W1);
    k_gate<<<BTOK / 8, 256>>>(x, wg);
    k_expert<<<dim3(HTILES, MTILES, NEXP), NTHR, SMEM_TOTAL>>>(W2, b1);
    k_combine<<<(BTOK + 255) / 256, 256>>>(out, b2);
}

// round 6
// speedup vs baseline: 2.3234x; 1.1807x over previous
#include <cuda_runtime.h>
#include <cuda_fp16.h>
#include <cstdint>
#include <cstddef>
#include <math.h>

// ---------------- problem constants ----------------
#define BTOK  16384
#define IND   512
#define HIDD  2048
#define NEXP  8
#define NTOP  4

// ---------------- tiling ----------------
#define TM      128               // tokens per block
#define TN      128               // hidden cols per block
#define NKB     (IND / 16)        // 32 k-blocks of K=16
#define KBPST   4                 // k-blocks per stage (K=64)
#define NST     3
#define NKCH    (NKB / KBPST)     // 8 mainloop iterations
#define HTILES  (HIDD / TN)       // 16
#define MTILES  (BTOK / TM)       // 128 (worst case)
#define NTHR    256

// packed-fragment stage sizes (fp16)
// A stage: 8 m-tiles x 4 kb x 32 lanes x 16B = 16384 B
// B stage: 16 h8-tiles x 4 kb x 32 lanes x 8B = 16384 B
#define A_BYTES 16384
#define B_BYTES 16384
#define STAGE_BYTES (A_BYTES + B_BYTES)       // 32768
#define SMEM_TOTAL  (NST * STAGE_BYTES)       // 98304  (2 CTAs/SM)

#define A_TILE_BYTES  16384    // one 16-row m-tile: 32 kb x 32 lanes x 16B
#define B_TILE_BYTES  8192     // one 8-col h-tile: 32 kb x 32 lanes x 8B

// ---------------- device scratch ----------------
// A packed (half2 as uint): [e][slot/16][kb][lane][4]
__device__ __align__(1024) uint32_t g_xcu[(size_t)NEXP * BTOK * IND / 2];
// B packed (half2 as uint): [e][h/8][kb][lane][2]
__device__ __align__(1024) uint32_t g_w1u[(size_t)NEXP * HIDD * IND / 2];
__device__ int   g_cnt[NEXP];
__device__ int   g_sel[BTOK * NTOP];
__device__ int   g_slot[BTOK * NTOP];
__device__ float g_g4[BTOK * NTOP];
__device__ float g_part[(size_t)NEXP * BTOK * HTILES];

// ---------------- helpers ----------------
__device__ __forceinline__ void cp_async16(uint32_t saddr, const void* gaddr) {
    asm volatile("cp.async.cg.shared.global [%0], [%1], 16;" :: "r"(saddr), "l"(gaddr) : "memory");
}

__device__ __forceinline__ uint32_t smem_u32(const void* p) {
    uint32_t a;
    asm("{ .reg .u64 t; cvta.to.shared.u64 t, %1; cvt.u32.u64 %0, t; }" : "=r"(a) : "l"(p));
    return a;
}

__device__ __forceinline__ void mma_f16(float* c, const uint32_t* a, const uint32_t* b) {
    asm volatile(
        "mma.sync.aligned.m16n8k16.row.col.f32.f16.f16.f32 "
        "{%0,%1,%2,%3}, {%4,%5,%6,%7}, {%8,%9}, {%0,%1,%2,%3};"
        : "+f"(c[0]), "+f"(c[1]), "+f"(c[2]), "+f"(c[3])
        : "r"(a[0]), "r"(a[1]), "r"(a[2]), "r"(a[3]), "r"(b[0]), "r"(b[1]));
}

// ============================================================
// kernel 0: zero counters
// ============================================================
__global__ void k_zero() {
    if (threadIdx.x < NEXP) g_cnt[threadIdx.x] = 0;
}

// ============================================================
// kernel 1: W1 -> packed fp16 B-fragment layout
// grid (16 h-chunks of 128, 32 kb, 8 e), 256 thr
// ============================================================
__global__ void k_transpose(const float* __restrict__ W1) {
    __shared__ float tile[16][129];
    int hc = blockIdx.x;      // 128-h chunk
    int kb = blockIdx.y;
    int e  = blockIdx.z;
    int tid = threadIdx.x;

    #pragma unroll
    for (int it = 0; it < 8; ++it) {
        int idx = tid + it * 256;
        int kr = idx >> 7, hf = idx & 127;
        tile[kr][hf] = W1[((size_t)e * IND + kb * 16 + kr) * HIDD + hc * 128 + hf];
    }
    __syncthreads();

    size_t base2 = (size_t)e * (HIDD * IND / 2);
    #pragma unroll
    for (int it = 0; it < 4; ++it) {
        int w    = tid + it * 256;
        int h8l  = w >> 6;
        int rem  = w & 63;
        int lane = rem >> 1, rj = rem & 1;
        int grp  = lane >> 2, qid = lane & 3;
        int hl   = h8l * 8 + grp;
        int k0   = rj * 8 + qid * 2;
        __half2 v = __floats2half2_rn(tile[k0][hl], tile[k0 + 1][hl]);
        g_w1u[base2 + (size_t)(hc * 16 + h8l) * 2048 + (kb * 32 + lane) * 2 + rj]
            = *(uint32_t*)&v;
    }
}

// ============================================================
// kernel 2: gating + top-4 + softmax + packed fp16 scatter
// one warp per token
// ============================================================
__global__ void k_gate(const float* __restrict__ x, const float* __restrict__ wg) {
    int warp = blockIdx.x * (blockDim.x >> 5) + (threadIdx.x >> 5);
    int lane = threadIdx.x & 31;
    if (warp >= BTOK) return;
    const float* xr = x + (size_t)warp * IND;

    float acc[NEXP];
    #pragma unroll
    for (int e = 0; e < NEXP; ++e) acc[e] = 0.f;
    for (int i = lane; i < IND; i += 32) {
        float xv = xr[i];
        #pragma unroll
        for (int e = 0; e < NEXP; ++e) acc[e] = fmaf(xv, wg[i * NEXP + e], acc[e]);
    }
    #pragma unroll
    for (int off = 16; off > 0; off >>= 1) {
        #pragma unroll
        for (int e = 0; e < NEXP; ++e)
            acc[e] += __shfl_xor_sync(0xFFFFFFFFu, acc[e], off);
    }

    // top-4: strict '>' keeps lowest index on ties (matches jax.lax.top_k)
    int   sel[NTOP];
    float val[NTOP];
    bool  used[NEXP];
    #pragma unroll
    for (int e = 0; e < NEXP; ++e) used[e] = false;
    #pragma unroll
    for (int k = 0; k < NTOP; ++k) {
        float best = -1e30f; int be = 0;
        #pragma unroll
        for (int e = 0; e < NEXP; ++e)
            if (!used[e] && acc[e] > best) { best = acc[e]; be = e; }
        used[be] = true; sel[k] = be; val[k] = best;
    }
    float s = 0.f, gt[NTOP];
    #pragma unroll
    for (int k = 0; k < NTOP; ++k) { gt[k] = expf(val[k] - val[0]); s += gt[k]; }
    float inv = 1.f / s;
    #pragma unroll
    for (int k = 0; k < NTOP; ++k) gt[k] *= inv;

    int slot[NTOP];
    if (lane == 0) {
        #pragma unroll
        for (int k = 0; k < NTOP; ++k) slot[k] = atomicAdd(&g_cnt[sel[k]], 1);
    }
    #pragma unroll
    for (int k = 0; k < NTOP; ++k) slot[k] = __shfl_sync(0xFFFFFFFFu, slot[k], 0);

    if (lane < NTOP) {
        g_sel[warp * NTOP + lane]  = sel[lane];
        g_slot[warp * NTOP + lane] = slot[lane];
        g_g4[warp * NTOP + lane]   = gt[lane];
    }

    uint32_t hv[8];
    #pragma unroll
    for (int it = 0; it < 8; ++it) {
        int p = lane + it * 32;
        __half2 v = __floats2half2_rn(xr[2 * p], xr[2 * p + 1]);
        hv[it] = *(uint32_t*)&v;
    }

    #pragma unroll
    for (int kk = 0; kk < NTOP; ++kk) {
        int sl = slot[kk];
        size_t base2 = (size_t)sel[kk] * (BTOK * IND / 2) + (size_t)(sl >> 4) * 4096;
        int r = sl & 15, grp = r & 7, rowhalf = r >> 3;
        #pragma unroll
        for (int it = 0; it < 8; ++it) {
            int p     = lane + it * 32;
            int kb    = p >> 3;
            int khalf = (p & 7) >> 2;
            int qid   = p & 3;
            g_xcu[base2 + (size_t)(kb * 32 + grp * 4 + qid) * 4 + rowhalf + 2 * khalf]
                = hv[it];
        }
    }
}

// ============================================================
// kernel 3: expert GEMM fp16 m16n8k16 (fc1 + relu + fc2-partial)
// grid (HTILES, MTILES, NEXP), 256 threads, 2 CTAs/SM
// ============================================================
__device__ __forceinline__ void load_stage(uint32_t sb, int s, int kt, int tid,
                                           const char* Ag, const char* Bg) {
    uint32_t abase = sb + (uint32_t)s * STAGE_BYTES;
    uint32_t bbase = abase + A_BYTES;
    // A: 1024 chunks of 16B (8 m-tiles)
    #pragma unroll
    for (int it = 0; it < 4; ++it) {
        int c    = tid + it * NTHR;
        int tile = c >> 7, rem = c & 127;
        cp_async16(abase + (uint32_t)c * 16,
                   Ag + (size_t)tile * A_TILE_BYTES + kt * 2048 + rem * 16);
    }
    // B: 1024 chunks of 16B (16 h8-tiles)
    #pragma unroll
    for (int it = 0; it < 4; ++it) {
        int c    = tid + it * NTHR;
        int tile = c >> 6, rem = c & 63;
        cp_async16(bbase + (uint32_t)c * 16,
                   Bg + (size_t)tile * B_TILE_BYTES + kt * 1024 + rem * 16);
    }
    asm volatile("cp.async.commit_group;" ::: "memory");
}

__global__ void __launch_bounds__(NTHR, 2)
k_expert(const float* __restrict__ W2, const float* __restrict__ b1) {
    extern __shared__ char smem[];
    const int e     = blockIdx.z;
    const int mtile = blockIdx.y;
    const int ht    = blockIdx.x;
    const int cnt   = g_cnt[e];
    const int m0    = mtile * TM;
    if (m0 >= cnt) return;

    const int tid  = threadIdx.x;
    const int wid  = tid >> 5;
    const int lane = tid & 31;
    const int wm   = wid >> 2;       // 0..1 : rows wm*64
    const int wn   = wid & 3;        // 0..3 : cols wn*32
    const int grp  = lane >> 2;
    const int qid  = lane & 3;

    uint32_t sb = smem_u32(smem);
    const char* Ag = (const char*)g_xcu + (size_t)e * (BTOK * IND * 2)
                   + (size_t)(m0 >> 4) * A_TILE_BYTES;
    const char* Bg = (const char*)g_w1u + (size_t)e * (HIDD * IND * 2)
                   + (size_t)(ht * (TN / 8)) * B_TILE_BYTES;

    float acc[4][4][4];
    #pragma unroll
    for (int mt = 0; mt < 4; ++mt)
        #pragma unroll
        for (int nt = 0; nt < 4; ++nt)
            #pragma unroll
            for (int r = 0; r < 4; ++r) acc[mt][nt][r] = 0.f;

    load_stage(sb, 0, 0, tid, Ag, Bg);
    load_stage(sb, 1, 1, tid, Ag, Bg);

    for (int kt = 0; kt < NKCH; ++kt) {
        asm volatile("cp.async.wait_group 1;" ::: "memory");
        __syncthreads();
        int kn = kt + 2;
        if (kn < NKCH) load_stage(sb, kn % NST, kn, tid, Ag, Bg);
        else asm volatile("cp.async.commit_group;" ::: "memory");

        const uint4* sA = (const uint4*)(smem + (size_t)(kt % NST) * STAGE_BYTES);
        const uint2* sB = (const uint2*)(smem + (size_t)(kt % NST) * STAGE_BYTES + A_BYTES);

        #pragma unroll
        for (int ks = 0; ks < KBPST; ++ks) {             // 4 K=16 steps
            uint4 af[4];
            uint2 bf[4];
            #pragma unroll
            for (int mt = 0; mt < 4; ++mt)
                af[mt] = sA[((wm * 4 + mt) * 4 + ks) * 32 + lane];
            #pragma unroll
            for (int nt = 0; nt < 4; ++nt)
                bf[nt] = sB[((wn * 4 + nt) * 4 + ks) * 32 + lane];
            #pragma unroll
            for (int mt = 0; mt < 4; ++mt)
                #pragma unroll
                for (int nt = 0; nt < 4; ++nt)
                    mma_f16(acc[mt][nt], (const uint32_t*)&af[mt], (const uint32_t*)&bf[nt]);
        }
    }
    __syncthreads();

    // ---- fused epilogue: relu(h + b1) . W2 over this 128-col tile ----
    float* red = (float*)smem;                 // [TM][4]
    float* w2s = (float*)(smem + TM * 4 * 4);  // [TN]
    float* b1s = w2s + TN;                     // [TN]
    if (tid < TN) {
        w2s[tid] = W2[(size_t)e * HIDD + ht * TN + tid];
        b1s[tid] = b1[(size_t)e * HIDD + ht * TN + tid];
    }
    __syncthreads();

    #pragma unroll
    for (int mt = 0; mt < 4; ++mt) {
        #pragma unroll
        for (int rr = 0; rr < 2; ++rr) {
            int row = wm * 64 + mt * 16 + grp + rr * 8;
            float v = 0.f;
            #pragma unroll
            for (int nt = 0; nt < 4; ++nt) {
                int col = wn * 32 + nt * 8 + qid * 2;
                float h0 = fmaxf(acc[mt][nt][rr * 2 + 0] + b1s[col], 0.f);
                float h1 = fmaxf(acc[mt][nt][rr * 2 + 1] + b1s[col + 1], 0.f);
                v = fmaf(h0, w2s[col], v);
                v = fmaf(h1, w2s[col + 1], v);
            }
            v += __shfl_down_sync(0xFFFFFFFFu, v, 2);
            v += __shfl_down_sync(0xFFFFFFFFu, v, 1);
            if (qid == 0) red[row * 4 + wn] = v;
        }
    }
    __syncthreads();

    if (tid < TM) {
        float p = red[tid * 4 + 0] + red[tid * 4 + 1] + red[tid * 4 + 2] + red[tid * 4 + 3];
        g_part[((size_t)e * BTOK + m0 + tid) * HTILES + ht] = p;
    }
}

// ============================================================
// kernel 4: weighted combine
// ============================================================
__global__ void k_combine(float* __restrict__ out, const float* __restrict__ b2) {
    int t = blockIdx.x * blockDim.x + threadIdx.x;
    if (t >= BTOK) return;
    float y = 0.f;
    #pragma unroll
    for (int k = 0; k < NTOP; ++k) {
        int   e = g_sel[t * NTOP + k];
        int   s = g_slot[t * NTOP + k];
        float g = g_g4[t * NTOP + k];
        float p = b2[e];
        const float* pp = &g_part[((size_t)e * BTOK + s) * HTILES];
        #pragma unroll
        for (int h = 0; h < HTILES; ++h) p += pp[h];
        y = fmaf(g, p, y);
    }
    out[t] = y;
}

// ============================================================
// launch
// ============================================================
extern "C" void kernel_launch(void* const* d_in, const int* in_sizes, int n_in,
                              void* d_out, int out_size) {
    const float* x  = (const float*)d_in[0];   // [16384, 512]
    const float* wg = (const float*)d_in[1];   // [512, 8]
    const float* W1 = (const float*)d_in[2];   // [8, 512, 2048]
    const float* b1 = (const float*)d_in[3];   // [8, 2048]
    const float* W2 = (const float*)d_in[4];   // [8, 2048, 1]
    const float* b2 = (const float*)d_in[5];   // [8, 1]
    float* out = (float*)d_out;                // [16384, 1]

    cudaFuncSetAttribute(k_expert, cudaFuncAttributeMaxDynamicSharedMemorySize, SMEM_TOTAL);

    k_zero<<<1, 32>>>();
    k_transpose<<<dim3(HIDD / 128, NKB, NEXP), 256>>>(W1);
    k_gate<<<BTOK / 8, 256>>>(x, wg);
    k_expert<<<dim3(HTILES, MTILES, NEXP), NTHR, SMEM_TOTAL>>>(W2, b1);
    k_combine<<<(BTOK + 255) / 256, 256>>>(out, b2);
}